// round 17
// baseline (speedup 1.0000x reference)
#include <cuda_runtime.h>
#include <cuda_fp16.h>
#include <cstdint>
#include <cstddef>

// ---------------------------------------------------------------------------
// Problem constants (fixed shapes per reference)
// ---------------------------------------------------------------------------
#define NU    100000
#define NI    50000
#define KDIM  256
#define MSGD  128
#define OUTD  128
#define RREL  5
#define NE    1000000
#define NCOMB (RREL * OUTD)   // 640

#define CAP_I 64              // bucket capacity per (r, item) — mean deg 20
#define CAP_U 40              // bucket capacity per (r, user) — mean deg 10
#define MAXOVF (1 << 20)

// GEMM smem layout (halfs)
#define LDK   264             // A row stride: 256 + 8 pad (528B, conflict-free ldmatrix)
#define LDB   136             // B stage row stride: 128 + 8 pad
#define LDT   136             // epilogue tile row stride
#define SMEM_A_OFF 0
#define SMEM_B_OFF (128 * LDK)                    // 33792
#define SMEM_T_OFF (SMEM_B_OFF + 2 * 16 * LDB)    // 38144
#define SMEM_HALFS (SMEM_T_OFF + 128 * LDT)       // 55552
#define SMEM_BYTES (SMEM_HALFS * 2)               // 111104

// ---------------------------------------------------------------------------
// Static device scratch (no runtime allocation allowed)
// ---------------------------------------------------------------------------
static __device__ __half g_xu[(size_t)RREL * NU * OUTD];  // messages fp16, [R][NU][128]
static __device__ __half g_xi[(size_t)RREL * NI * OUTD];  // messages fp16, [R][NI][128]
static __device__ __half g_wcu[KDIM * NCOMB];             // combined weights fp16
static __device__ __half g_wci[KDIM * NCOMB];

static __device__ int g_cnt_i[RREL * NI];
static __device__ int g_cnt_u[RREL * NU];
static __device__ int g_bkt_i[(size_t)RREL * NI * CAP_I];
static __device__ int g_bkt_u[(size_t)RREL * NU * CAP_U];
static __device__ int g_ovf_i[MAXOVF];
static __device__ int g_ovf_u[MAXOVF];
static __device__ int g_ovfcnt[2];

// ---------------------------------------------------------------------------
// Kernel 1: combine weights -> fp16  Wc[k][r*128+o] = sum_m W[r,k,m]*Wfc[r*128+m,o]
// ---------------------------------------------------------------------------
__global__ void combine_w_kernel(const float* __restrict__ W,
                                 const float* __restrict__ Wfc,
                                 __half* __restrict__ Wc)
{
    int idx = blockIdx.x * blockDim.x + threadIdx.x;
    if (idx >= KDIM * NCOMB) return;
    int k = idx / NCOMB;
    int c = idx - k * NCOMB;
    int r = c / OUTD;
    int o = c - r * OUTD;
    const float* wrow = W + ((size_t)r * KDIM + k) * MSGD;
    const float* fc   = Wfc + ((size_t)r * MSGD) * OUTD + o;
    float s = 0.f;
#pragma unroll 8
    for (int m = 0; m < MSGD; ++m)
        s += wrow[m] * fc[(size_t)m * OUTD];
    Wc[idx] = __float2half_rn(s);
}

// ---------------------------------------------------------------------------
// Zero helpers
// ---------------------------------------------------------------------------
__global__ void zero_int_kernel(int4* __restrict__ p, int n4)
{
    int i = blockIdx.x * blockDim.x + threadIdx.x;
    if (i < n4) p[i] = make_int4(0, 0, 0, 0);
}

__global__ void zero_ovf_kernel(int* p)
{
    if (threadIdx.x < 2) p[threadIdx.x] = 0;
}

// ---------------------------------------------------------------------------
// fp16 helpers
// ---------------------------------------------------------------------------
__device__ __forceinline__ uint2 f4_to_h4(float4 v)
{
    __half2 lo = __float22half2_rn(make_float2(v.x, v.y));
    __half2 hi = __float22half2_rn(make_float2(v.z, v.w));
    uint2 r;
    r.x = *(uint32_t*)&lo;
    r.y = *(uint32_t*)&hi;
    return r;
}

// ---------------------------------------------------------------------------
// Kernel 3: FP16 tensor-core GEMM with A-tile reuse across all 5 relations.
// One CTA per 128-row block: A (128x256 fp16) loaded into smem ONCE, then
// loop r=0..4 streaming B[r] (fp16, L2-resident) -> X[r][rows][128].
// ---------------------------------------------------------------------------
__global__ __launch_bounds__(256, 2) void gemm_f16_kernel(
    const float* __restrict__ A,    // [M, 256] fp32
    const __half* __restrict__ Bw,  // [256, 640] fp16 (combined weights)
    const float* __restrict__ cj,   // [M]
    __half* __restrict__ X,         // [R][M][128] fp16
    int M)
{
    extern __shared__ __align__(16) __half sm[];
    __half* As = sm + SMEM_A_OFF;   // [128][LDK]
    __half* Bs = sm + SMEM_B_OFF;   // [2][16][LDB]
    __half* Ts = sm + SMEM_T_OFF;   // [128][LDT]

    const int t    = threadIdx.x;
    const int lane = t & 31;
    const int warp = t >> 5;
    const int wm   = (warp >> 2) * 64;     // 0 or 64
    const int wn   = (warp & 3) * 32;      // 0,32,64,96
    const int rowBase = blockIdx.x * 128;

    // ---- load full A tile fp32 -> fp16 (once) ----
#pragma unroll
    for (int i = 0; i < 32; ++i) {
        int idx = i * 256 + t;              // 8192 float4 total
        int row = idx >> 6;                 // 64 float4 per row
        int k   = (idx & 63) << 2;
        int gr  = rowBase + row;
        float4 v = (gr < M) ? *(const float4*)(A + (size_t)gr * KDIM + k)
                            : make_float4(0.f, 0.f, 0.f, 0.f);
        *(uint2*)&As[row * LDK + k] = f4_to_h4(v);
    }

    // hoist cj scale factors (same rows for every relation)
    float cs0[4], cs1[4];
#pragma unroll
    for (int mt = 0; mt < 4; ++mt) {
        int r0 = rowBase + wm + mt * 16 + (lane >> 2);
        int r1 = r0 + 8;
        cs0[mt] = (r0 < M) ? __ldg(cj + r0) : 0.f;
        cs1[mt] = (r1 < M) ? __ldg(cj + r1) : 0.f;
    }
    __syncthreads();

    const int aLdRow = wm + (lane & 15);
    const int aLdK   = ((lane >> 4) & 1) * 8;
    const int bLdK   = lane & 15;
    const int bLdN   = ((lane >> 4) & 1) * 8;
    const int bRow   = t >> 5;              // 0..7 (plus +8)
    const int bCol   = (t & 31) << 2;       // 0..124

    const uint32_t asb = (uint32_t)__cvta_generic_to_shared(As);

    for (int r = 0; r < RREL; ++r) {
        const __half* Bp = Bw + r * 128;    // row stride NCOMB

        float acc[4][4][4];
#pragma unroll
        for (int mt = 0; mt < 4; ++mt)
#pragma unroll
            for (int nt = 0; nt < 4; ++nt)
#pragma unroll
                for (int c = 0; c < 4; ++c) acc[mt][nt][c] = 0.f;

        // prologue: B stage 0
        {
            uint2 b0 = *(const uint2*)(Bp + (size_t)bRow * NCOMB + bCol);
            uint2 b1 = *(const uint2*)(Bp + (size_t)(bRow + 8) * NCOMB + bCol);
            *(uint2*)&Bs[bRow * LDB + bCol]       = b0;
            *(uint2*)&Bs[(bRow + 8) * LDB + bCol] = b1;
        }
        __syncthreads();

        for (int s = 0; s < 16; ++s) {
            uint2 pb0, pb1;
            const int nxt = s + 1;
            if (nxt < 16) {
                const int k0 = nxt * 16;
                pb0 = *(const uint2*)(Bp + (size_t)(k0 + bRow) * NCOMB + bCol);
                pb1 = *(const uint2*)(Bp + (size_t)(k0 + bRow + 8) * NCOMB + bCol);
            }

            const uint32_t bsb = (uint32_t)__cvta_generic_to_shared(
                Bs + (s & 1) * 16 * LDB);

            uint32_t af[4][4];
#pragma unroll
            for (int mt = 0; mt < 4; ++mt) {
                uint32_t addr = asb +
                    (uint32_t)(((aLdRow + mt * 16) * LDK + s * 16 + aLdK) * 2);
                asm volatile(
                    "ldmatrix.sync.aligned.m8n8.x4.shared.b16 {%0,%1,%2,%3}, [%4];"
                    : "=r"(af[mt][0]), "=r"(af[mt][1]),
                      "=r"(af[mt][2]), "=r"(af[mt][3])
                    : "r"(addr));
            }
            uint32_t bf[4][2];
#pragma unroll
            for (int np = 0; np < 2; ++np) {
                uint32_t addr = bsb +
                    (uint32_t)((bLdK * LDB + wn + np * 16 + bLdN) * 2);
                uint32_t r0, r1, r2, r3;
                asm volatile(
                    "ldmatrix.sync.aligned.m8n8.x4.trans.shared.b16 {%0,%1,%2,%3}, [%4];"
                    : "=r"(r0), "=r"(r1), "=r"(r2), "=r"(r3)
                    : "r"(addr));
                bf[np * 2 + 0][0] = r0; bf[np * 2 + 0][1] = r1;
                bf[np * 2 + 1][0] = r2; bf[np * 2 + 1][1] = r3;
            }

#pragma unroll
            for (int mt = 0; mt < 4; ++mt)
#pragma unroll
                for (int nt = 0; nt < 4; ++nt) {
                    asm volatile(
                        "mma.sync.aligned.m16n8k16.row.col.f32.f16.f16.f32 "
                        "{%0,%1,%2,%3}, {%4,%5,%6,%7}, {%8,%9}, {%0,%1,%2,%3};"
                        : "+f"(acc[mt][nt][0]), "+f"(acc[mt][nt][1]),
                          "+f"(acc[mt][nt][2]), "+f"(acc[mt][nt][3])
                        : "r"(af[mt][0]), "r"(af[mt][1]),
                          "r"(af[mt][2]), "r"(af[mt][3]),
                          "r"(bf[nt][0]), "r"(bf[nt][1]));
                }

            if (nxt < 16) {
                __half* bsn = Bs + (nxt & 1) * 16 * LDB;
                *(uint2*)&bsn[bRow * LDB + bCol]       = pb0;
                *(uint2*)&bsn[(bRow + 8) * LDB + bCol] = pb1;
            }
            __syncthreads();
        }

        // ---- epilogue: scale by cj, stage fp16 tile, coalesced store ----
#pragma unroll
        for (int mt = 0; mt < 4; ++mt) {
            const int lr0 = wm + mt * 16 + (lane >> 2);
            const int lr1 = lr0 + 8;
#pragma unroll
            for (int nt = 0; nt < 4; ++nt) {
                const int col = wn + nt * 8 + (lane & 3) * 2;
                *(half2*)&Ts[lr0 * LDT + col] =
                    __floats2half2_rn(acc[mt][nt][0] * cs0[mt],
                                      acc[mt][nt][1] * cs0[mt]);
                *(half2*)&Ts[lr1 * LDT + col] =
                    __floats2half2_rn(acc[mt][nt][2] * cs1[mt],
                                      acc[mt][nt][3] * cs1[mt]);
            }
        }
        __syncthreads();

        __half* Xr = X + ((size_t)r * M + rowBase) * OUTD;
#pragma unroll
        for (int idx = t; idx < 128 * 16; idx += 256) {
            int row = idx >> 4;
            int seg = idx & 15;
            if (rowBase + row < M)
                *(uint4*)(Xr + (size_t)row * OUTD + seg * 8) =
                    *(const uint4*)&Ts[row * LDT + seg * 8];
        }
        __syncthreads();
    }
}

// ---------------------------------------------------------------------------
// Kernel 4a: bin edges by (relation, dst); 2 edges per thread for MLP.
// ---------------------------------------------------------------------------
template <int N, int CAP>
__global__ __launch_bounds__(256) void bin_kernel(
    const int* __restrict__ dstArr,   // [R*E]
    const int* __restrict__ srcArr,   // [R*E]
    int* __restrict__ cnt,            // [R*N]
    int* __restrict__ bkt,            // [R*N*CAP]
    int* __restrict__ ovf,
    int* __restrict__ ovfcnt)
{
    int g = blockIdx.x * 256 + threadIdx.x;
    int w0 = 2 * g;
    if (w0 >= RREL * NE) return;
    int2 d2 = *(const int2*)(dstArr + w0);
    int2 s2 = *(const int2*)(srcArr + w0);

    {
        int r = w0 / NE;
        int key = r * N + d2.x;
        int pos = atomicAdd(&cnt[key], 1);
        if (pos < CAP) bkt[(size_t)key * CAP + pos] = s2.x;
        else {
            int o = atomicAdd(ovfcnt, 1);
            if (o < MAXOVF) ovf[o] = w0;
        }
    }
    {
        int w1 = w0 + 1;
        int r = w1 / NE;
        int key = r * N + d2.y;
        int pos = atomicAdd(&cnt[key], 1);
        if (pos < CAP) bkt[(size_t)key * CAP + pos] = s2.y;
        else {
            int o = atomicAdd(ovfcnt, 1);
            if (o < MAXOVF) ovf[o] = w1;
        }
    }
}

// ---------------------------------------------------------------------------
// Kernel 4b: fused gather + finalize. One warp per destination node.
// ---------------------------------------------------------------------------
template <int N, int CAP, int MSRC>
__global__ __launch_bounds__(256) void gather_out_kernel(
    const __half* __restrict__ X,     // [R][MSRC][128] fp16
    const int* __restrict__ cnt,      // [R*N]
    const int* __restrict__ bkt,      // [R*N*CAP]
    const float* __restrict__ ci,     // [N]
    const float* __restrict__ bias,   // [128]
    float* __restrict__ out)          // [N, 128]
{
    int dst = blockIdx.x * 8 + (threadIdx.x >> 5);
    if (dst >= N) return;
    int lane = threadIdx.x & 31;
    const __half* Xl = X + (size_t)lane * 4;

    float4 s = make_float4(0.f, 0.f, 0.f, 0.f);
#pragma unroll
    for (int r = 0; r < RREL; ++r) {
        int key = r * N + dst;
        int n = cnt[key];
        int m = n < CAP ? n : CAP;
        const int* b = bkt + (size_t)key * CAP;
        const __half* Xr = Xl + (size_t)r * MSRC * OUTD;
#pragma unroll 8
        for (int i = 0; i < m; ++i) {
            int src = b[i];
            uint2 raw = *(const uint2*)(Xr + (size_t)src * OUTD);
            float2 f0 = __half22float2(*(const __half2*)&raw.x);
            float2 f1 = __half22float2(*(const __half2*)&raw.y);
            s.x += f0.x; s.y += f0.y; s.z += f1.x; s.w += f1.y;
        }
    }

    float c = ci[dst];
    float4 bb = *(const float4*)(bias + lane * 4);
    float4 o;
    o.x = s.x * c + bb.x; o.y = s.y * c + bb.y;
    o.z = s.z * c + bb.z; o.w = s.w * c + bb.w;
    *(float4*)(out + (size_t)dst * OUTD + lane * 4) = o;
}

// ---------------------------------------------------------------------------
// Kernel 4c: overflow fallback (expected empty): red.add ci*msg into out.
// ---------------------------------------------------------------------------
template <int MSRC>
__global__ __launch_bounds__(256) void ovf_kernel(
    const __half* __restrict__ X,
    const int* __restrict__ srcArr,
    const int* __restrict__ dstArr,
    const int* __restrict__ ovf,
    const int* __restrict__ ovfcnt,
    const float* __restrict__ ci,
    float* __restrict__ out)
{
    int nov = *ovfcnt;
    if (nov > MAXOVF) nov = MAXOVF;
    int lane = threadIdx.x & 31;
    for (int idx = blockIdx.x * 8 + (threadIdx.x >> 5); idx < nov;
         idx += gridDim.x * 8) {
        int w = ovf[idx];
        int r = w / NE;
        int src = srcArr[w];
        int dst = dstArr[w];
        float c = ci[dst];
        uint2 raw = *(const uint2*)(X + ((size_t)r * MSRC + src) * OUTD + lane * 4);
        float2 f0 = __half22float2(*(const __half2*)&raw.x);
        float2 f1 = __half22float2(*(const __half2*)&raw.y);
        float* ap = out + (size_t)dst * OUTD + lane * 4;
        asm volatile("red.global.add.v4.f32 [%0], {%1, %2, %3, %4};"
                     :: "l"(ap), "f"(f0.x * c), "f"(f0.y * c),
                        "f"(f1.x * c), "f"(f1.y * c)
                     : "memory");
    }
}

// ---------------------------------------------------------------------------
// Host launcher — bins on aux stream overlap GEMMs; join before gathers.
// ---------------------------------------------------------------------------
extern "C" void kernel_launch(void* const* d_in, const int* in_sizes, int n_in,
                              void* d_out, int out_size)
{
    const float* ufeat   = (const float*)d_in[0];
    const float* ifeat   = (const float*)d_in[1];
    const float* cj_user = (const float*)d_in[2];
    const float* ci_user = (const float*)d_in[3];
    const float* cj_item = (const float*)d_in[4];
    const float* ci_item = (const float*)d_in[5];
    const float* W_u     = (const float*)d_in[6];
    const float* W_i     = (const float*)d_in[7];
    const float* Wu_fc   = (const float*)d_in[8];
    const float* bu      = (const float*)d_in[9];
    const float* Wi_fc   = (const float*)d_in[10];
    const float* bi      = (const float*)d_in[11];
    const int*   edge_u  = (const int*)d_in[12];
    const int*   edge_i  = (const int*)d_in[13];
    float* out = (float*)d_out;
    float* out_u = out;
    float* out_i = out + (size_t)NU * OUTD;

    __half *xu, *xi, *wcu, *wci;
    int *cnt_i, *cnt_u, *bkt_i, *bkt_u, *ovf_i, *ovf_u, *ovfc;
    cudaGetSymbolAddress((void**)&xu,    g_xu);
    cudaGetSymbolAddress((void**)&xi,    g_xi);
    cudaGetSymbolAddress((void**)&wcu,   g_wcu);
    cudaGetSymbolAddress((void**)&wci,   g_wci);
    cudaGetSymbolAddress((void**)&cnt_i, g_cnt_i);
    cudaGetSymbolAddress((void**)&cnt_u, g_cnt_u);
    cudaGetSymbolAddress((void**)&bkt_i, g_bkt_i);
    cudaGetSymbolAddress((void**)&bkt_u, g_bkt_u);
    cudaGetSymbolAddress((void**)&ovf_i, g_ovf_i);
    cudaGetSymbolAddress((void**)&ovf_u, g_ovf_u);
    cudaGetSymbolAddress((void**)&ovfc,  g_ovfcnt);

    // One-time infra (created on the uncaptured correctness call).
    static cudaStream_t s_aux = nullptr;
    static cudaEvent_t ev_fork = nullptr, ev_join = nullptr;
    if (s_aux == nullptr) {
        cudaStreamCreateWithFlags(&s_aux, cudaStreamNonBlocking);
        cudaEventCreateWithFlags(&ev_fork, cudaEventDisableTiming);
        cudaEventCreateWithFlags(&ev_join, cudaEventDisableTiming);
        cudaFuncSetAttribute(gemm_f16_kernel,
                             cudaFuncAttributeMaxDynamicSharedMemorySize,
                             SMEM_BYTES);
    }

    // ---- fork: aux stream joins the capture DAG ----
    cudaEventRecord(ev_fork, 0);
    cudaStreamWaitEvent(s_aux, ev_fork, 0);

    // ---- aux stream: zero counters, then bin edges ----
    zero_int_kernel<<<((RREL * NI / 4) + 255) / 256, 256, 0, s_aux>>>(
        (int4*)cnt_i, RREL * NI / 4);
    zero_int_kernel<<<((RREL * NU / 4) + 255) / 256, 256, 0, s_aux>>>(
        (int4*)cnt_u, RREL * NU / 4);
    zero_ovf_kernel<<<1, 32, 0, s_aux>>>(ovfc);
    int bblocks = (RREL * NE / 2 + 255) / 256;
    bin_kernel<NI, CAP_I><<<bblocks, 256, 0, s_aux>>>(
        edge_i, edge_u, cnt_i, bkt_i, ovf_i, ovfc + 0);
    bin_kernel<NU, CAP_U><<<bblocks, 256, 0, s_aux>>>(
        edge_u, edge_i, cnt_u, bkt_u, ovf_u, ovfc + 1);

    // ---- main stream: combine weights (fp16), then A-reuse GEMMs ----
    int ctotal = KDIM * NCOMB;
    combine_w_kernel<<<(ctotal + 255) / 256, 256>>>(W_u, Wi_fc, wcu);
    combine_w_kernel<<<(ctotal + 255) / 256, 256>>>(W_i, Wu_fc, wci);

    gemm_f16_kernel<<<(NU + 127) / 128, 256, SMEM_BYTES>>>(
        ufeat, wcu, cj_user, xu, NU);
    gemm_f16_kernel<<<(NI + 127) / 128, 256, SMEM_BYTES>>>(
        ifeat, wci, cj_item, xi, NI);

    // ---- join: gathers need both bins and GEMMs ----
    cudaEventRecord(ev_join, s_aux);
    cudaStreamWaitEvent(0, ev_join, 0);

    // ---- fused gather + finalize, straight into d_out ----
    gather_out_kernel<NI, CAP_I, NU><<<(NI + 7) / 8, 256>>>(
        xu, cnt_i, bkt_i, ci_item, bi, out_i);
    gather_out_kernel<NU, CAP_U, NI><<<(NU + 7) / 8, 256>>>(
        xi, cnt_u, bkt_u, ci_user, bu, out_u);

    // ---- overflow fallback (normally zero work) ----
    ovf_kernel<NU><<<64, 256>>>(xu, edge_u, edge_i, ovf_i, ovfc + 0, ci_item, out_i);
    ovf_kernel<NI><<<64, 256>>>(xi, edge_i, edge_u, ovf_u, ovfc + 1, ci_user, out_u);
}